// round 3
// baseline (speedup 1.0000x reference)
#include <cuda_runtime.h>
#include <cstdint>
#include <cfloat>

// Problem constants
#define BB   4
#define NN   2048
#define MM   2048
#define HH   16
#define DHH  64
#define IDD  1024   // H*DH
#define QDD  1024
#define SCALE 0.125f   // 64^-0.5
#define MAXNEG (-3.402823466e38f)

// Scratch (allocation-free rule: __device__ globals)
__device__ float g_Q[BB * NN * IDD];   // 32 MB
__device__ float g_K[BB * MM * IDD];   // 32 MB
__device__ float g_V[BB * MM * IDD];   // 32 MB
__device__ float g_AO[BB * NN * IDD];  // 32 MB

// ---------------------------------------------------------------------------
// Tiled fp32 SGEMM: C[R x 1024] = A[R x 1024] @ W[1024 x 1024] (+ bias)
// 128x128 tile, BK=8, 256 threads, 8x8 microtile
// ---------------------------------------------------------------------------
__global__ __launch_bounds__(256) void sgemm128(
    const float* __restrict__ A, const float* __restrict__ W,
    const float* __restrict__ bias, float* __restrict__ C)
{
    __shared__ float As[8][128];   // transposed: As[k][row]
    __shared__ float Bs[8][132];   // Bs[k][col], padded

    const int tid  = threadIdx.x;
    const int tx   = tid & 15;
    const int ty   = tid >> 4;
    const int row0 = blockIdx.y * 128;
    const int col0 = blockIdx.x * 128;

    float acc[8][8];
#pragma unroll
    for (int i = 0; i < 8; i++)
#pragma unroll
        for (int j = 0; j < 8; j++) acc[i][j] = 0.f;

    const int e  = tid * 4;
    const int ar = e >> 3;       // A row within tile
    const int ak = e & 7;        // A k within tile (0 or 4)
    const int bk = e >> 7;       // B k within tile
    const int bc = e & 127;      // B col within tile

    for (int kt = 0; kt < 1024; kt += 8) {
        float4 av = *reinterpret_cast<const float4*>(
            A + (size_t)(row0 + ar) * 1024 + kt + ak);
        As[ak + 0][ar] = av.x;
        As[ak + 1][ar] = av.y;
        As[ak + 2][ar] = av.z;
        As[ak + 3][ar] = av.w;

        float4 bv = *reinterpret_cast<const float4*>(
            W + (size_t)(kt + bk) * 1024 + col0 + bc);
        *reinterpret_cast<float4*>(&Bs[bk][bc]) = bv;

        __syncthreads();

#pragma unroll
        for (int kk = 0; kk < 8; kk++) {
            float4 a0 = *reinterpret_cast<const float4*>(&As[kk][ty * 8]);
            float4 a1 = *reinterpret_cast<const float4*>(&As[kk][ty * 8 + 4]);
            float4 b0 = *reinterpret_cast<const float4*>(&Bs[kk][tx * 8]);
            float4 b1 = *reinterpret_cast<const float4*>(&Bs[kk][tx * 8 + 4]);
            float af[8] = {a0.x, a0.y, a0.z, a0.w, a1.x, a1.y, a1.z, a1.w};
            float bf[8] = {b0.x, b0.y, b0.z, b0.w, b1.x, b1.y, b1.z, b1.w};
#pragma unroll
            for (int i = 0; i < 8; i++)
#pragma unroll
                for (int j = 0; j < 8; j++)
                    acc[i][j] += af[i] * bf[j];
        }
        __syncthreads();
    }

    // epilogue
#pragma unroll
    for (int i = 0; i < 8; i++) {
        const int row = row0 + ty * 8 + i;
        float* cp = C + (size_t)row * 1024 + col0 + tx * 8;
        float out[8];
#pragma unroll
        for (int j = 0; j < 8; j++) out[j] = acc[i][j];
        if (bias) {
#pragma unroll
            for (int j = 0; j < 8; j++) out[j] += bias[col0 + tx * 8 + j];
        }
        *reinterpret_cast<float4*>(cp)     = make_float4(out[0], out[1], out[2], out[3]);
        *reinterpret_cast<float4*>(cp + 4) = make_float4(out[4], out[5], out[6], out[7]);
    }
}

// ---------------------------------------------------------------------------
// Flash attention: one CTA per (b, h, 64-query tile).
// Online softmax over M in 64-key chunks.
// ---------------------------------------------------------------------------
#define ATT_SMEM_FLOATS (4096 + 4160 + 4160 + 4160 + 4 * 64)
#define ATT_SMEM_BYTES  (ATT_SMEM_FLOATS * 4)

__global__ __launch_bounds__(256) void attn_kernel(
    const float* __restrict__ Q, const float* __restrict__ K,
    const float* __restrict__ V, const int* __restrict__ mask,
    float* __restrict__ AO)
{
    extern __shared__ float sm[];
    float* Qs   = sm;                 // [64][64]   stride 64
    float* KT   = Qs + 4096;          // [d][k]     stride 65
    float* Vs   = KT + 4160;          // [k][d]     stride 65
    float* Ss   = Vs + 4160;          // [q][c]     stride 65
    float* mrow = Ss + 4160;          // [64]
    float* lrow = mrow + 64;
    float* arow = lrow + 64;
    float* mskf = arow + 64;          // 1.0 = masked out

    const int tid = threadIdx.x;
    const int tx  = tid & 15;
    const int ty  = tid >> 4;
    const int n0  = blockIdx.x * 64;
    const int h   = blockIdx.y;
    const int b   = blockIdx.z;

    // load Q tile [64 q][64 d]
    for (int idx = tid; idx < 4096; idx += 256) {
        const int q = idx >> 6, d = idx & 63;
        Qs[q * 64 + d] =
            Q[((size_t)b * NN + (n0 + q)) * IDD + h * DHH + d];
    }
    if (tid < 64) { mrow[tid] = MAXNEG; lrow[tid] = 0.f; }

    float o[4][4];
#pragma unroll
    for (int i = 0; i < 4; i++)
#pragma unroll
        for (int j = 0; j < 4; j++) o[i][j] = 0.f;

    for (int j0 = 0; j0 < MM; j0 += 64) {
        if (tid < 64)
            mskf[tid] = (mask[(size_t)b * MM + j0 + tid] != 0) ? 0.f : 1.f;

        // load K (transposed) and V chunks
        for (int idx = tid; idx < 4096; idx += 256) {
            const int k = idx >> 6, d = idx & 63;
            const size_t g = ((size_t)b * MM + (j0 + k)) * IDD + h * DHH + d;
            KT[d * 65 + k] = K[g];
            Vs[k * 65 + d] = V[g];
        }
        __syncthreads();

        // S = Q @ K^T  (4x4 per thread)
        float s[4][4];
#pragma unroll
        for (int i = 0; i < 4; i++)
#pragma unroll
            for (int j = 0; j < 4; j++) s[i][j] = 0.f;

#pragma unroll 8
        for (int d = 0; d < 64; d++) {
            float qf[4], kf[4];
#pragma unroll
            for (int i = 0; i < 4; i++) qf[i] = Qs[(ty * 4 + i) * 64 + d];
#pragma unroll
            for (int j = 0; j < 4; j++) kf[j] = KT[d * 65 + tx * 4 + j];
#pragma unroll
            for (int i = 0; i < 4; i++)
#pragma unroll
                for (int j = 0; j < 4; j++)
                    s[i][j] += qf[i] * kf[j];
        }

        // write S (scaled + masked) into smem
#pragma unroll
        for (int j = 0; j < 4; j++) {
            const int c = tx * 4 + j;
            const bool dead = (mskf[c] != 0.f);
#pragma unroll
            for (int i = 0; i < 4; i++)
                Ss[(ty * 4 + i) * 65 + c] = dead ? MAXNEG : s[i][j] * SCALE;
        }
        __syncthreads();

        // row softmax (online), one row per thread (tid < 64)
        if (tid < 64) {
            float* row  = Ss + tid * 65;
            const float mold = mrow[tid];
            float mc = mold;
#pragma unroll 8
            for (int c = 0; c < 64; c++) mc = fmaxf(mc, row[c]);
            const float al = __expf(mold - mc);
            float l = lrow[tid] * al;
#pragma unroll 8
            for (int c = 0; c < 64; c++) {
                const float p = __expf(row[c] - mc);
                row[c] = p;
                l += p;
            }
            mrow[tid] = mc; lrow[tid] = l; arow[tid] = al;
        }
        __syncthreads();

        // rescale O, accumulate O += P @ V
        float ai[4];
#pragma unroll
        for (int i = 0; i < 4; i++) ai[i] = arow[ty * 4 + i];
#pragma unroll
        for (int i = 0; i < 4; i++)
#pragma unroll
            for (int j = 0; j < 4; j++) o[i][j] *= ai[i];

#pragma unroll 8
        for (int kk = 0; kk < 64; kk++) {
            float pf[4], vf[4];
#pragma unroll
            for (int i = 0; i < 4; i++) pf[i] = Ss[(ty * 4 + i) * 65 + kk];
#pragma unroll
            for (int j = 0; j < 4; j++) vf[j] = Vs[kk * 65 + tx * 4 + j];
#pragma unroll
            for (int i = 0; i < 4; i++)
#pragma unroll
                for (int j = 0; j < 4; j++)
                    o[i][j] += pf[i] * vf[j];
        }
        __syncthreads();   // before next chunk overwrites KT/Vs/Ss/mskf
    }

    // normalize and write (B, N, H*DH)
#pragma unroll
    for (int i = 0; i < 4; i++) {
        const float linv = 1.f / lrow[ty * 4 + i];
        const size_t base =
            ((size_t)b * NN + (n0 + ty * 4 + i)) * IDD + h * DHH + tx * 4;
#pragma unroll
        for (int j = 0; j < 4; j++)
            AO[base + j] = o[i][j] * linv;
    }
}

// ---------------------------------------------------------------------------
// Launch
// ---------------------------------------------------------------------------
extern "C" void kernel_launch(void* const* d_in, const int* in_sizes, int n_in,
                              void* d_out, int out_size)
{
    const float* x    = (const float*)d_in[0];
    const float* ctx  = (const float*)d_in[1];
    const int*   mask = (const int*)d_in[2];     // bool -> int32 in harness
    const float* Wq   = (const float*)d_in[3];
    const float* Wk   = (const float*)d_in[4];
    const float* Wv   = (const float*)d_in[5];
    const float* Wo   = (const float*)d_in[6];
    const float* bo   = (const float*)d_in[7];
    float* out        = (float*)d_out;

    float *Qp, *Kp, *Vp, *AOp;
    cudaGetSymbolAddress((void**)&Qp,  g_Q);
    cudaGetSymbolAddress((void**)&Kp,  g_K);
    cudaGetSymbolAddress((void**)&Vp,  g_V);
    cudaGetSymbolAddress((void**)&AOp, g_AO);

    cudaFuncSetAttribute(attn_kernel,
                         cudaFuncAttributeMaxDynamicSharedMemorySize,
                         ATT_SMEM_BYTES);

    const dim3 gg(1024 / 128, (BB * NN) / 128);   // (8, 64)
    const dim3 bk(256);

    sgemm128<<<gg, bk>>>(x,   Wq, nullptr, Qp);
    sgemm128<<<gg, bk>>>(ctx, Wk, nullptr, Kp);
    sgemm128<<<gg, bk>>>(ctx, Wv, nullptr, Vp);

    attn_kernel<<<dim3(NN / 64, HH, BB), 256, ATT_SMEM_BYTES>>>(
        Qp, Kp, Vp, mask, AOp);

    sgemm128<<<gg, bk>>>(AOp, Wo, bo, out);
}

// round 4
// speedup vs baseline: 3.3060x; 3.3060x over previous
#include <cuda_runtime.h>
#include <cstdint>

#define BB   4
#define NN   2048
#define MM   2048
#define HH   16
#define DHH  64
#define IDD  1024
#define SCALE 0.125f
#define MAXNEG (-3.402823466e38f)

__device__ float g_Q[BB * NN * IDD];
__device__ float g_K[BB * MM * IDD];
__device__ float g_V[BB * MM * IDD];
__device__ float g_AO[BB * NN * IDD];

// ---------------------------------------------------------------------------
// helpers
// ---------------------------------------------------------------------------
__device__ __forceinline__ uint32_t f2t(float x) {
    uint32_t u;
    asm("cvt.rna.tf32.f32 %0, %1;" : "=r"(u) : "f"(x));
    return u;
}

__device__ __forceinline__ void mma8(float* c,
    uint32_t a0, uint32_t a1, uint32_t a2, uint32_t a3,
    uint32_t b0, uint32_t b1)
{
    asm volatile(
        "mma.sync.aligned.m16n8k8.row.col.f32.tf32.tf32.f32 "
        "{%0,%1,%2,%3}, {%4,%5,%6,%7}, {%8,%9}, {%0,%1,%2,%3};"
        : "+f"(c[0]), "+f"(c[1]), "+f"(c[2]), "+f"(c[3])
        : "r"(a0), "r"(a1), "r"(a2), "r"(a3), "r"(b0), "r"(b1));
}

// ---------------------------------------------------------------------------
// TF32 GEMM: C[8192 x 1024] = A[8192 x 1024] @ W[1024 x 1024] (+bias)
// 128x128x32 tile, 256 threads, warp tile 64x32
// ---------------------------------------------------------------------------
#define ASP 36    // As stride (m-major [128][36])  — banks 4g+tig: conflict-free
#define BSP 136   // Bs stride (k-major [32][136])  — banks 8tig+g: conflict-free

__global__ __launch_bounds__(256) void gemm_tf32(
    const float* __restrict__ A, const float* __restrict__ W,
    const float* __restrict__ bias, float* __restrict__ C)
{
    __shared__ uint32_t As[128 * ASP];
    __shared__ uint32_t Bs[32 * BSP];

    const int tid  = threadIdx.x;
    const int lane = tid & 31;
    const int wid  = tid >> 5;
    const int g    = lane >> 2;
    const int tig  = lane & 3;
    const int wm   = wid & 1;    // 2 warps in M
    const int wn   = wid >> 1;   // 4 warps in N
    const int row0 = blockIdx.y * 128;
    const int col0 = blockIdx.x * 128;

    float acc[4][4][4];
#pragma unroll
    for (int mi = 0; mi < 4; mi++)
#pragma unroll
        for (int ni = 0; ni < 4; ni++)
#pragma unroll
            for (int r = 0; r < 4; r++) acc[mi][ni][r] = 0.f;

    for (int kt = 0; kt < 1024; kt += 32) {
        // fill A tile (m-major), coalesced float4 along k
#pragma unroll
        for (int i = 0; i < 4; i++) {
            const int f  = tid + i * 256;     // 1024 float4 slots
            const int r  = f >> 3;            // 0..127
            const int k4 = f & 7;             // 0..7
            const float4 v = *reinterpret_cast<const float4*>(
                A + (size_t)(row0 + r) * 1024 + kt + k4 * 4);
            *reinterpret_cast<uint4*>(&As[r * ASP + k4 * 4]) =
                make_uint4(f2t(v.x), f2t(v.y), f2t(v.z), f2t(v.w));
        }
        // fill B tile (k-major), coalesced float4 along n
#pragma unroll
        for (int i = 0; i < 4; i++) {
            const int f  = tid + i * 256;
            const int k  = f >> 5;            // 0..31
            const int n4 = f & 31;            // 0..31
            const float4 v = *reinterpret_cast<const float4*>(
                W + (size_t)(kt + k) * 1024 + col0 + n4 * 4);
            *reinterpret_cast<uint4*>(&Bs[k * BSP + n4 * 4]) =
                make_uint4(f2t(v.x), f2t(v.y), f2t(v.z), f2t(v.w));
        }
        __syncthreads();

#pragma unroll
        for (int kk = 0; kk < 32; kk += 8) {
            uint32_t af[4][4];
#pragma unroll
            for (int mi = 0; mi < 4; mi++) {
                const int m0 = wm * 64 + mi * 16;
                af[mi][0] = As[(m0 + g)     * ASP + kk + tig];
                af[mi][1] = As[(m0 + g + 8) * ASP + kk + tig];
                af[mi][2] = As[(m0 + g)     * ASP + kk + tig + 4];
                af[mi][3] = As[(m0 + g + 8) * ASP + kk + tig + 4];
            }
#pragma unroll
            for (int ni = 0; ni < 4; ni++) {
                const int n0 = wn * 32 + ni * 8;
                const uint32_t b0 = Bs[(kk + tig)     * BSP + n0 + g];
                const uint32_t b1 = Bs[(kk + tig + 4) * BSP + n0 + g];
#pragma unroll
                for (int mi = 0; mi < 4; mi++)
                    mma8(acc[mi][ni], af[mi][0], af[mi][1], af[mi][2], af[mi][3], b0, b1);
            }
        }
        __syncthreads();
    }

    // epilogue
#pragma unroll
    for (int mi = 0; mi < 4; mi++) {
        const int rA = row0 + wm * 64 + mi * 16 + g;
#pragma unroll
        for (int ni = 0; ni < 4; ni++) {
            const int col = col0 + wn * 32 + ni * 8 + 2 * tig;
            float b0v = 0.f, b1v = 0.f;
            if (bias) { b0v = bias[col]; b1v = bias[col + 1]; }
            *reinterpret_cast<float2*>(&C[(size_t)rA * 1024 + col]) =
                make_float2(acc[mi][ni][0] + b0v, acc[mi][ni][1] + b1v);
            *reinterpret_cast<float2*>(&C[(size_t)(rA + 8) * 1024 + col]) =
                make_float2(acc[mi][ni][2] + b0v, acc[mi][ni][3] + b1v);
        }
    }
}

// ---------------------------------------------------------------------------
// TF32 flash attention: CTA = 128 queries x (b,h); 64-key chunks.
// 8 warps, warp owns 16 query rows. S and P@V via mma.sync.
// ---------------------------------------------------------------------------
#define QSP 68   // smem stride: banks 4g+tig conflict-free, rows 16B-aligned

#define ATT_SMEM_BYTES ((128 * QSP + 64 * QSP + 64 * QSP + 128 * QSP) * 4 + 256)

__global__ __launch_bounds__(256) void attn_tc(
    const float* __restrict__ Q, const float* __restrict__ K,
    const float* __restrict__ V, const int* __restrict__ mask,
    float* __restrict__ AO)
{
    extern __shared__ uint32_t sm[];
    uint32_t* Qs = sm;                  // [128][QSP] tf32 bits (pre-scaled)
    uint32_t* Ks = Qs + 128 * QSP;      // [64][QSP]
    uint32_t* Vs = Ks + 64 * QSP;       // [64][QSP]
    uint32_t* Ss = Vs + 64 * QSP;       // [128][QSP] P as tf32 bits
    int*      msk = (int*)(Ss + 128 * QSP);   // [64]

    const int tid  = threadIdx.x;
    const int lane = tid & 31;
    const int wid  = tid >> 5;
    const int g    = lane >> 2;
    const int tig  = lane & 3;
    const int n0   = blockIdx.x * 128;
    const int h    = blockIdx.y;
    const int b    = blockIdx.z;
    const int q0   = wid * 16;          // warp's query rows [q0, q0+16)

    // fill Q (scaled by SCALE), coalesced
#pragma unroll
    for (int i = 0; i < 8; i++) {
        const int f  = tid + i * 256;   // 2048 float4 slots
        const int r  = f >> 4;          // 0..127
        const int d4 = f & 15;          // 0..15
        const float4 v = *reinterpret_cast<const float4*>(
            Q + ((size_t)b * NN + n0 + r) * IDD + h * 64 + d4 * 4);
        *reinterpret_cast<uint4*>(&Qs[r * QSP + d4 * 4]) =
            make_uint4(f2t(v.x * SCALE), f2t(v.y * SCALE),
                       f2t(v.z * SCALE), f2t(v.w * SCALE));
    }

    float o[8][4];
#pragma unroll
    for (int nf = 0; nf < 8; nf++)
#pragma unroll
        for (int r = 0; r < 4; r++) o[nf][r] = 0.f;
    float mA = MAXNEG, mB = MAXNEG, lA = 0.f, lB = 0.f;

    for (int j0 = 0; j0 < MM; j0 += 64) {
        __syncthreads();   // prior chunk done with Ks/Vs (also covers Qs fill)

        // fill K, V chunk (tf32), coalesced
#pragma unroll
        for (int i = 0; i < 4; i++) {
            const int f  = tid + i * 256;   // 1024 float4 slots each
            const int r  = f >> 4;
            const int d4 = f & 15;
            const size_t gb = ((size_t)b * MM + j0 + r) * IDD + h * 64 + d4 * 4;
            const float4 kv = *reinterpret_cast<const float4*>(K + gb);
            *reinterpret_cast<uint4*>(&Ks[r * QSP + d4 * 4]) =
                make_uint4(f2t(kv.x), f2t(kv.y), f2t(kv.z), f2t(kv.w));
            const float4 vv = *reinterpret_cast<const float4*>(V + gb);
            *reinterpret_cast<uint4*>(&Vs[r * QSP + d4 * 4]) =
                make_uint4(f2t(vv.x), f2t(vv.y), f2t(vv.z), f2t(vv.w));
        }
        if (tid < 64) msk[tid] = mask[(size_t)b * MM + j0 + tid];
        __syncthreads();

        // S = Q @ K^T  (already scaled via Q)
        float s[8][4];
#pragma unroll
        for (int nf = 0; nf < 8; nf++)
#pragma unroll
            for (int r = 0; r < 4; r++) s[nf][r] = 0.f;

#pragma unroll
        for (int ks = 0; ks < 8; ks++) {
            const int d0 = ks * 8;
            const uint32_t a0 = Qs[(q0 + g)     * QSP + d0 + tig];
            const uint32_t a1 = Qs[(q0 + g + 8) * QSP + d0 + tig];
            const uint32_t a2 = Qs[(q0 + g)     * QSP + d0 + tig + 4];
            const uint32_t a3 = Qs[(q0 + g + 8) * QSP + d0 + tig + 4];
#pragma unroll
            for (int nf = 0; nf < 8; nf++) {
                const int jc = nf * 8;
                const uint32_t b0 = Ks[(jc + g) * QSP + d0 + tig];
                const uint32_t b1 = Ks[(jc + g) * QSP + d0 + tig + 4];
                mma8(s[nf], a0, a1, a2, a3, b0, b1);
            }
        }

        // mask + online softmax (rows q0+g and q0+g+8)
        float cmA = MAXNEG, cmB = MAXNEG;
#pragma unroll
        for (int nf = 0; nf < 8; nf++) {
            const int c0 = nf * 8 + 2 * tig;
            if (!msk[c0])     { s[nf][0] = MAXNEG; s[nf][2] = MAXNEG; }
            if (!msk[c0 + 1]) { s[nf][1] = MAXNEG; s[nf][3] = MAXNEG; }
            cmA = fmaxf(cmA, fmaxf(s[nf][0], s[nf][1]));
            cmB = fmaxf(cmB, fmaxf(s[nf][2], s[nf][3]));
        }
        cmA = fmaxf(cmA, __shfl_xor_sync(0xffffffffu, cmA, 1));
        cmA = fmaxf(cmA, __shfl_xor_sync(0xffffffffu, cmA, 2));
        cmB = fmaxf(cmB, __shfl_xor_sync(0xffffffffu, cmB, 1));
        cmB = fmaxf(cmB, __shfl_xor_sync(0xffffffffu, cmB, 2));

        const float mnA = fmaxf(mA, cmA);
        const float mnB = fmaxf(mB, cmB);
        const float alA = __expf(mA - mnA);
        const float alB = __expf(mB - mnB);
        mA = mnA; mB = mnB;

        float suA = 0.f, suB = 0.f;
#pragma unroll
        for (int nf = 0; nf < 8; nf++) {
            const float p0 = __expf(s[nf][0] - mnA);
            const float p1 = __expf(s[nf][1] - mnA);
            const float p2 = __expf(s[nf][2] - mnB);
            const float p3 = __expf(s[nf][3] - mnB);
            suA += p0 + p1;
            suB += p2 + p3;
            const int c0 = nf * 8 + 2 * tig;
            *reinterpret_cast<uint2*>(&Ss[(q0 + g)     * QSP + c0]) =
                make_uint2(f2t(p0), f2t(p1));
            *reinterpret_cast<uint2*>(&Ss[(q0 + g + 8) * QSP + c0]) =
                make_uint2(f2t(p2), f2t(p3));
        }
        suA += __shfl_xor_sync(0xffffffffu, suA, 1);
        suA += __shfl_xor_sync(0xffffffffu, suA, 2);
        suB += __shfl_xor_sync(0xffffffffu, suB, 1);
        suB += __shfl_xor_sync(0xffffffffu, suB, 2);
        lA = lA * alA + suA;
        lB = lB * alB + suB;

#pragma unroll
        for (int nf = 0; nf < 8; nf++) {
            o[nf][0] *= alA; o[nf][1] *= alA;
            o[nf][2] *= alB; o[nf][3] *= alB;
        }
        __syncwarp();   // P stores visible to whole warp (rows are warp-private)

        // O += P @ V
#pragma unroll
        for (int ks = 0; ks < 8; ks++) {
            const int s0 = ks * 8;
            const uint32_t a0 = Ss[(q0 + g)     * QSP + s0 + tig];
            const uint32_t a1 = Ss[(q0 + g + 8) * QSP + s0 + tig];
            const uint32_t a2 = Ss[(q0 + g)     * QSP + s0 + tig + 4];
            const uint32_t a3 = Ss[(q0 + g + 8) * QSP + s0 + tig + 4];
#pragma unroll
            for (int nf = 0; nf < 8; nf++) {
                const int d0 = nf * 8;
                const uint32_t b0 = Vs[(s0 + tig)     * QSP + d0 + g];
                const uint32_t b1 = Vs[(s0 + tig + 4) * QSP + d0 + g];
                mma8(o[nf], a0, a1, a2, a3, b0, b1);
            }
        }
    }

    // normalize + write
    const float liA = 1.f / lA;
    const float liB = 1.f / lB;
#pragma unroll
    for (int nf = 0; nf < 8; nf++) {
        const int col = h * 64 + nf * 8 + 2 * tig;
        const size_t rA = ((size_t)b * NN + n0 + q0 + g)     * IDD + col;
        const size_t rB = ((size_t)b * NN + n0 + q0 + g + 8) * IDD + col;
        *reinterpret_cast<float2*>(&AO[rA]) =
            make_float2(o[nf][0] * liA, o[nf][1] * liA);
        *reinterpret_cast<float2*>(&AO[rB]) =
            make_float2(o[nf][2] * liB, o[nf][3] * liB);
    }
}

// ---------------------------------------------------------------------------
// Launch
// ---------------------------------------------------------------------------
extern "C" void kernel_launch(void* const* d_in, const int* in_sizes, int n_in,
                              void* d_out, int out_size)
{
    const float* x    = (const float*)d_in[0];
    const float* ctx  = (const float*)d_in[1];
    const int*   mask = (const int*)d_in[2];
    const float* Wq   = (const float*)d_in[3];
    const float* Wk   = (const float*)d_in[4];
    const float* Wv   = (const float*)d_in[5];
    const float* Wo   = (const float*)d_in[6];
    const float* bo   = (const float*)d_in[7];
    float* out        = (float*)d_out;

    float *Qp, *Kp, *Vp, *AOp;
    cudaGetSymbolAddress((void**)&Qp,  g_Q);
    cudaGetSymbolAddress((void**)&Kp,  g_K);
    cudaGetSymbolAddress((void**)&Vp,  g_V);
    cudaGetSymbolAddress((void**)&AOp, g_AO);

    cudaFuncSetAttribute(attn_tc,
                         cudaFuncAttributeMaxDynamicSharedMemorySize,
                         ATT_SMEM_BYTES);

    const dim3 gg(1024 / 128, (BB * NN) / 128);   // (8, 64)
    const dim3 bk(256);

    gemm_tf32<<<gg, bk>>>(x,   Wq, nullptr, Qp);
    gemm_tf32<<<gg, bk>>>(ctx, Wk, nullptr, Kp);
    gemm_tf32<<<gg, bk>>>(ctx, Wv, nullptr, Vp);

    attn_tc<<<dim3(NN / 128, HH, BB), 256, ATT_SMEM_BYTES>>>(
        Qp, Kp, Vp, mask, AOp);

    gemm_tf32<<<gg, bk>>>(AOp, Wo, bo, out);
}

// round 5
// speedup vs baseline: 3.4928x; 1.0565x over previous
#include <cuda_runtime.h>
#include <cstdint>

#define BB   4
#define NN   2048
#define MM   2048
#define HH   16
#define DHH  64
#define IDD  1024
#define SCALE 0.125f
#define MAXNEG (-3.402823466e38f)

__device__ float g_Q[BB * NN * IDD];
__device__ float g_K[BB * MM * IDD];
__device__ float g_V[BB * MM * IDD];
__device__ float g_AO[BB * NN * IDD];

// ---------------------------------------------------------------------------
// helpers
// ---------------------------------------------------------------------------
__device__ __forceinline__ uint32_t f2t(float x) {
    uint32_t u;
    asm("cvt.rna.tf32.f32 %0, %1;" : "=r"(u) : "f"(x));
    return u;
}

__device__ __forceinline__ void mma8(float* c,
    uint32_t a0, uint32_t a1, uint32_t a2, uint32_t a3,
    uint32_t b0, uint32_t b1)
{
    asm volatile(
        "mma.sync.aligned.m16n8k8.row.col.f32.tf32.tf32.f32 "
        "{%0,%1,%2,%3}, {%4,%5,%6,%7}, {%8,%9}, {%0,%1,%2,%3};"
        : "+f"(c[0]), "+f"(c[1]), "+f"(c[2]), "+f"(c[3])
        : "r"(a0), "r"(a1), "r"(a2), "r"(a3), "r"(b0), "r"(b1));
}

// ldmatrix x4 of b32 data viewed as 8x8 b16 matrices (bit movement only)
__device__ __forceinline__ void ldsm4(uint32_t* r, uint32_t saddr) {
    asm volatile("ldmatrix.sync.aligned.m8n8.x4.shared.b16 {%0,%1,%2,%3}, [%4];"
        : "=r"(r[0]), "=r"(r[1]), "=r"(r[2]), "=r"(r[3]) : "r"(saddr));
}

// ---------------------------------------------------------------------------
// TF32 GEMM: C[8192 x 1024] = A[8192 x 1024] @ W[1024 x 1024] (+bias)
// 128x128x32 tile, 256 threads, warp tile 64x32. A frags via ldmatrix.
// ---------------------------------------------------------------------------
#define ASP 36
#define BSP 136

__global__ __launch_bounds__(256) void gemm_tf32(
    const float* __restrict__ A, const float* __restrict__ W,
    const float* __restrict__ bias, float* __restrict__ C)
{
    __shared__ uint32_t As[128 * ASP];
    __shared__ uint32_t Bs[32 * BSP];

    const int tid  = threadIdx.x;
    const int lane = tid & 31;
    const int wid  = tid >> 5;
    const int g    = lane >> 2;
    const int tig  = lane & 3;
    const int wm   = wid & 1;
    const int wn   = wid >> 1;
    const int row0 = blockIdx.y * 128;
    const int col0 = blockIdx.x * 128;

    // ldmatrix lane offsets (A-type fragment)
    const int arow = lane & 15;
    const int acol = (lane >> 4) * 4;
    const uint32_t As_base = (uint32_t)__cvta_generic_to_shared(As);

    float acc[4][4][4];
#pragma unroll
    for (int mi = 0; mi < 4; mi++)
#pragma unroll
        for (int ni = 0; ni < 4; ni++)
#pragma unroll
            for (int r = 0; r < 4; r++) acc[mi][ni][r] = 0.f;

    for (int kt = 0; kt < 1024; kt += 32) {
#pragma unroll
        for (int i = 0; i < 4; i++) {
            const int f  = tid + i * 256;
            const int r  = f >> 3;
            const int k4 = f & 7;
            const float4 v = *reinterpret_cast<const float4*>(
                A + (size_t)(row0 + r) * 1024 + kt + k4 * 4);
            *reinterpret_cast<uint4*>(&As[r * ASP + k4 * 4]) =
                make_uint4(f2t(v.x), f2t(v.y), f2t(v.z), f2t(v.w));
        }
#pragma unroll
        for (int i = 0; i < 4; i++) {
            const int f  = tid + i * 256;
            const int k  = f >> 5;
            const int n4 = f & 31;
            const float4 v = *reinterpret_cast<const float4*>(
                W + (size_t)(kt + k) * 1024 + col0 + n4 * 4);
            *reinterpret_cast<uint4*>(&Bs[k * BSP + n4 * 4]) =
                make_uint4(f2t(v.x), f2t(v.y), f2t(v.z), f2t(v.w));
        }
        __syncthreads();

#pragma unroll
        for (int kk = 0; kk < 32; kk += 8) {
            uint32_t af[4][4];
#pragma unroll
            for (int mi = 0; mi < 4; mi++) {
                const int m0 = wm * 64 + mi * 16;
                ldsm4(af[mi], As_base + ((m0 + arow) * ASP + acol + kk) * 4);
            }
#pragma unroll
            for (int ni = 0; ni < 4; ni++) {
                const int n0 = wn * 32 + ni * 8;
                const uint32_t b0 = Bs[(kk + tig)     * BSP + n0 + g];
                const uint32_t b1 = Bs[(kk + tig + 4) * BSP + n0 + g];
#pragma unroll
                for (int mi = 0; mi < 4; mi++)
                    mma8(acc[mi][ni], af[mi][0], af[mi][1], af[mi][2], af[mi][3], b0, b1);
            }
        }
        __syncthreads();
    }

#pragma unroll
    for (int mi = 0; mi < 4; mi++) {
        const int rA = row0 + wm * 64 + mi * 16 + g;
#pragma unroll
        for (int ni = 0; ni < 4; ni++) {
            const int col = col0 + wn * 32 + ni * 8 + 2 * tig;
            float b0v = 0.f, b1v = 0.f;
            if (bias) { b0v = bias[col]; b1v = bias[col + 1]; }
            *reinterpret_cast<float2*>(&C[(size_t)rA * 1024 + col]) =
                make_float2(acc[mi][ni][0] + b0v, acc[mi][ni][1] + b1v);
            *reinterpret_cast<float2*>(&C[(size_t)(rA + 8) * 1024 + col]) =
                make_float2(acc[mi][ni][2] + b0v, acc[mi][ni][3] + b1v);
        }
    }
}

// ---------------------------------------------------------------------------
// TF32 flash attention: CTA = 256 queries x (b,h); 8 warps, warp owns 32 rows
// (two m16 tiles). 64-key chunks. ldmatrix for Q/K/P fragments.
// ---------------------------------------------------------------------------
#define QSP 68

#define ATT_SMEM_BYTES ((256 * QSP + 64 * QSP + 64 * QSP + 256 * QSP) * 4 + 256)

__global__ __launch_bounds__(256) void attn_tc(
    const float* __restrict__ Q, const float* __restrict__ K,
    const float* __restrict__ V, const int* __restrict__ mask,
    float* __restrict__ AO)
{
    extern __shared__ uint32_t sm[];
    uint32_t* Qs = sm;                   // [256][QSP]
    uint32_t* Ks = Qs + 256 * QSP;       // [64][QSP]
    uint32_t* Vs = Ks + 64 * QSP;        // [64][QSP]
    uint32_t* Ss = Vs + 64 * QSP;        // [256][QSP]
    int*      msk = (int*)(Ss + 256 * QSP);

    const int tid  = threadIdx.x;
    const int lane = tid & 31;
    const int wid  = tid >> 5;
    const int g    = lane >> 2;
    const int tig  = lane & 3;
    const int n0   = blockIdx.x * 256;
    const int h    = blockIdx.y;
    const int b    = blockIdx.z;
    const int q0   = wid * 32;

    // ldmatrix lane offsets
    const int arow = lane & 15;                    // A-type (Q, P)
    const int acol = (lane >> 4) * 4;
    const int krow = (lane & 7) + ((lane >> 4) << 3);   // B-type (K)
    const int kcol = (lane & 8) ? 4 : 0;
    const uint32_t Qs_b = (uint32_t)__cvta_generic_to_shared(Qs);
    const uint32_t Ks_b = (uint32_t)__cvta_generic_to_shared(Ks);
    const uint32_t Ss_b = (uint32_t)__cvta_generic_to_shared(Ss);

    // fill Q (scaled), coalesced: 256 rows x 16 float4
#pragma unroll
    for (int i = 0; i < 16; i++) {
        const int f  = tid + i * 256;
        const int r  = f >> 4;
        const int d4 = f & 15;
        const float4 v = *reinterpret_cast<const float4*>(
            Q + ((size_t)b * NN + n0 + r) * IDD + h * 64 + d4 * 4);
        *reinterpret_cast<uint4*>(&Qs[r * QSP + d4 * 4]) =
            make_uint4(f2t(v.x * SCALE), f2t(v.y * SCALE),
                       f2t(v.z * SCALE), f2t(v.w * SCALE));
    }

    float o[2][8][4];
#pragma unroll
    for (int t = 0; t < 2; t++)
#pragma unroll
        for (int nf = 0; nf < 8; nf++)
#pragma unroll
            for (int r = 0; r < 4; r++) o[t][nf][r] = 0.f;
    float mr[2][2], lr[2][2];
#pragma unroll
    for (int t = 0; t < 2; t++) {
        mr[t][0] = MAXNEG; mr[t][1] = MAXNEG;
        lr[t][0] = 0.f;    lr[t][1] = 0.f;
    }

    for (int j0 = 0; j0 < MM; j0 += 64) {
        __syncthreads();   // prev chunk done with Ks/Vs (covers Qs fill on c0)

#pragma unroll
        for (int i = 0; i < 4; i++) {
            const int f  = tid + i * 256;
            const int r  = f >> 4;
            const int d4 = f & 15;
            const size_t gb = ((size_t)b * MM + j0 + r) * IDD + h * 64 + d4 * 4;
            const float4 kv = *reinterpret_cast<const float4*>(K + gb);
            *reinterpret_cast<uint4*>(&Ks[r * QSP + d4 * 4]) =
                make_uint4(f2t(kv.x), f2t(kv.y), f2t(kv.z), f2t(kv.w));
            const float4 vv = *reinterpret_cast<const float4*>(V + gb);
            *reinterpret_cast<uint4*>(&Vs[r * QSP + d4 * 4]) =
                make_uint4(f2t(vv.x), f2t(vv.y), f2t(vv.z), f2t(vv.w));
        }
        if (tid < 64) msk[tid] = mask[(size_t)b * MM + j0 + tid];
        __syncthreads();

        // ---- S = Q @ K^T ----
        float s[2][8][4];
#pragma unroll
        for (int t = 0; t < 2; t++)
#pragma unroll
            for (int nf = 0; nf < 8; nf++)
#pragma unroll
                for (int r = 0; r < 4; r++) s[t][nf][r] = 0.f;

#pragma unroll
        for (int ks = 0; ks < 8; ks++) {
            const int d0 = ks * 8;
            uint32_t qa[2][4];
            ldsm4(qa[0], Qs_b + ((q0 + arow)      * QSP + acol + d0) * 4);
            ldsm4(qa[1], Qs_b + ((q0 + 16 + arow) * QSP + acol + d0) * 4);
#pragma unroll
            for (int np = 0; np < 4; np++) {
                const int jc = np * 16;
                uint32_t kb[4];
                ldsm4(kb, Ks_b + ((jc + krow) * QSP + kcol + d0) * 4);
                mma8(s[0][2*np],   qa[0][0], qa[0][1], qa[0][2], qa[0][3], kb[0], kb[1]);
                mma8(s[0][2*np+1], qa[0][0], qa[0][1], qa[0][2], qa[0][3], kb[2], kb[3]);
                mma8(s[1][2*np],   qa[1][0], qa[1][1], qa[1][2], qa[1][3], kb[0], kb[1]);
                mma8(s[1][2*np+1], qa[1][0], qa[1][1], qa[1][2], qa[1][3], kb[2], kb[3]);
            }
        }

        // ---- mask + online softmax + P->smem (per tile) ----
#pragma unroll
        for (int t = 0; t < 2; t++) {
            float cmA = MAXNEG, cmB = MAXNEG;
#pragma unroll
            for (int nf = 0; nf < 8; nf++) {
                const int c0 = nf * 8 + 2 * tig;
                if (!msk[c0])     { s[t][nf][0] = MAXNEG; s[t][nf][2] = MAXNEG; }
                if (!msk[c0 + 1]) { s[t][nf][1] = MAXNEG; s[t][nf][3] = MAXNEG; }
                cmA = fmaxf(cmA, fmaxf(s[t][nf][0], s[t][nf][1]));
                cmB = fmaxf(cmB, fmaxf(s[t][nf][2], s[t][nf][3]));
            }
            cmA = fmaxf(cmA, __shfl_xor_sync(0xffffffffu, cmA, 1));
            cmA = fmaxf(cmA, __shfl_xor_sync(0xffffffffu, cmA, 2));
            cmB = fmaxf(cmB, __shfl_xor_sync(0xffffffffu, cmB, 1));
            cmB = fmaxf(cmB, __shfl_xor_sync(0xffffffffu, cmB, 2));

            const float mnA = fmaxf(mr[t][0], cmA);
            const float mnB = fmaxf(mr[t][1], cmB);
            const float alA = __expf(mr[t][0] - mnA);
            const float alB = __expf(mr[t][1] - mnB);
            mr[t][0] = mnA; mr[t][1] = mnB;

            float suA = 0.f, suB = 0.f;
            const int rA = q0 + t * 16 + g;
#pragma unroll
            for (int nf = 0; nf < 8; nf++) {
                const float p0 = __expf(s[t][nf][0] - mnA);
                const float p1 = __expf(s[t][nf][1] - mnA);
                const float p2 = __expf(s[t][nf][2] - mnB);
                const float p3 = __expf(s[t][nf][3] - mnB);
                suA += p0 + p1;
                suB += p2 + p3;
                const int c0 = nf * 8 + 2 * tig;
                *reinterpret_cast<uint2*>(&Ss[rA       * QSP + c0]) =
                    make_uint2(f2t(p0), f2t(p1));
                *reinterpret_cast<uint2*>(&Ss[(rA + 8) * QSP + c0]) =
                    make_uint2(f2t(p2), f2t(p3));
            }
            suA += __shfl_xor_sync(0xffffffffu, suA, 1);
            suA += __shfl_xor_sync(0xffffffffu, suA, 2);
            suB += __shfl_xor_sync(0xffffffffu, suB, 1);
            suB += __shfl_xor_sync(0xffffffffu, suB, 2);
            lr[t][0] = lr[t][0] * alA + suA;
            lr[t][1] = lr[t][1] * alB + suB;

#pragma unroll
            for (int nf = 0; nf < 8; nf++) {
                o[t][nf][0] *= alA; o[t][nf][1] *= alA;
                o[t][nf][2] *= alB; o[t][nf][3] *= alB;
            }
        }
        __syncwarp();   // P stores visible within warp (rows warp-private)

        // ---- O += P @ V ----
#pragma unroll
        for (int ks = 0; ks < 8; ks++) {
            const int s0 = ks * 8;
            uint32_t pa[2][4];
            ldsm4(pa[0], Ss_b + ((q0 + arow)      * QSP + acol + s0) * 4);
            ldsm4(pa[1], Ss_b + ((q0 + 16 + arow) * QSP + acol + s0) * 4);
#pragma unroll
            for (int nf = 0; nf < 8; nf++) {
                const int d0 = nf * 8;
                const uint32_t b0 = Vs[(s0 + tig)     * QSP + d0 + g];
                const uint32_t b1 = Vs[(s0 + tig + 4) * QSP + d0 + g];
                mma8(o[0][nf], pa[0][0], pa[0][1], pa[0][2], pa[0][3], b0, b1);
                mma8(o[1][nf], pa[1][0], pa[1][1], pa[1][2], pa[1][3], b0, b1);
            }
        }
    }

    // normalize + write
#pragma unroll
    for (int t = 0; t < 2; t++) {
        const float liA = 1.f / lr[t][0];
        const float liB = 1.f / lr[t][1];
        const int rq = q0 + t * 16 + g;
#pragma unroll
        for (int nf = 0; nf < 8; nf++) {
            const int col = h * 64 + nf * 8 + 2 * tig;
            const size_t rA = ((size_t)b * NN + n0 + rq)     * IDD + col;
            const size_t rB = ((size_t)b * NN + n0 + rq + 8) * IDD + col;
            *reinterpret_cast<float2*>(&AO[rA]) =
                make_float2(o[t][nf][0] * liA, o[t][nf][1] * liA);
            *reinterpret_cast<float2*>(&AO[rB]) =
                make_float2(o[t][nf][2] * liB, o[t][nf][3] * liB);
        }
    }
}

// ---------------------------------------------------------------------------
// Launch
// ---------------------------------------------------------------------------
extern "C" void kernel_launch(void* const* d_in, const int* in_sizes, int n_in,
                              void* d_out, int out_size)
{
    const float* x    = (const float*)d_in[0];
    const float* ctx  = (const float*)d_in[1];
    const int*   mask = (const int*)d_in[2];
    const float* Wq   = (const float*)d_in[3];
    const float* Wk   = (const float*)d_in[4];
    const float* Wv   = (const float*)d_in[5];
    const float* Wo   = (const float*)d_in[6];
    const float* bo   = (const float*)d_in[7];
    float* out        = (float*)d_out;

    float *Qp, *Kp, *Vp, *AOp;
    cudaGetSymbolAddress((void**)&Qp,  g_Q);
    cudaGetSymbolAddress((void**)&Kp,  g_K);
    cudaGetSymbolAddress((void**)&Vp,  g_V);
    cudaGetSymbolAddress((void**)&AOp, g_AO);

    cudaFuncSetAttribute(attn_tc,
                         cudaFuncAttributeMaxDynamicSharedMemorySize,
                         ATT_SMEM_BYTES);

    const dim3 gg(1024 / 128, (BB * NN) / 128);   // (8, 64)
    const dim3 bk(256);

    gemm_tf32<<<gg, bk>>>(x,   Wq, nullptr, Qp);
    gemm_tf32<<<gg, bk>>>(ctx, Wk, nullptr, Kp);
    gemm_tf32<<<gg, bk>>>(ctx, Wv, nullptr, Vp);

    attn_tc<<<dim3(NN / 256, HH, BB), 256, ATT_SMEM_BYTES>>>(
        Qp, Kp, Vp, mask, AOp);

    gemm_tf32<<<gg, bk>>>(AOp, Wo, bo, out);
}